// round 9
// baseline (speedup 1.0000x reference)
#include <cuda_runtime.h>
#include <cuda_fp16.h>
#include <cstdint>
#include <math.h>

#define T_STEPS 512
#define BATCH   64
#define IN_DIM  1024
#define HID     1024
#define GATES   4096
#define NCTA    128
#define M_TOT   (T_STEPS * BATCH)      // 32768
#define FLAG_TARGET (NCTA * 4)         // per-warp arrivals

// ---------------- static scratch ----------------
__device__ __half g_Xh[(size_t)M_TOT * IN_DIM];            // 64 MB (fp16 x)
__device__ __half g_Wth[(size_t)GATES * IN_DIM];           // 8 MB  [n][k] fp16
__device__ float    g_xw[(size_t)T_STEPS * BATCH * GATES]; // 512 MB (x@Wx + b)
__device__ uint32_t g_hfrag[(size_t)T_STEPS * 32768];      // 64 MB (h fp16, mma A-frag layout)
__device__ int      g_flags[T_STEPS];

// ---------------- helpers ----------------
__device__ __forceinline__ uint32_t pack2h(__half a, __half b) {
    __half2 t = __halves2half2(a, b);
    return *reinterpret_cast<uint32_t*>(&t);
}
__device__ __forceinline__ void mma16816h(float* c, const uint32_t* a, const uint32_t* b) {
    asm volatile(
        "mma.sync.aligned.m16n8k16.row.col.f32.f16.f16.f32 "
        "{%0,%1,%2,%3}, {%4,%5,%6,%7}, {%8,%9}, {%0,%1,%2,%3};\n"
        : "+f"(c[0]), "+f"(c[1]), "+f"(c[2]), "+f"(c[3])
        : "r"(a[0]), "r"(a[1]), "r"(a[2]), "r"(a[3]), "r"(b[0]), "r"(b[1]));
}
__device__ __forceinline__ void ldsm_x4(uint32_t* r, uint32_t saddr) {
    asm volatile("ldmatrix.sync.aligned.m8n8.x4.shared.b16 {%0,%1,%2,%3}, [%4];\n"
        : "=r"(r[0]), "=r"(r[1]), "=r"(r[2]), "=r"(r[3]) : "r"(saddr));
}
__device__ __forceinline__ void cpasync16(uint32_t s, const void* g) {
    asm volatile("cp.async.cg.shared.global [%0], [%1], 16;\n" :: "r"(s), "l"(g));
}
#define CP_COMMIT() asm volatile("cp.async.commit_group;\n")
#define CP_WAIT1()  asm volatile("cp.async.wait_group 1;\n")

__device__ __forceinline__ void flag_release_add(int* p) {
    asm volatile("red.release.gpu.global.add.s32 [%0], %1;" :: "l"(p), "r"(1) : "memory");
}
__device__ __forceinline__ int flag_acquire_ld(const int* p) {
    int v;
    asm volatile("ld.acquire.gpu.global.s32 %0, [%1];" : "=r"(v) : "l"(p) : "memory");
    return v;
}

// =====================================================================
// Converters (reset flags; x -> fp16; Wx -> [n][k] fp16)
// =====================================================================
__global__ __launch_bounds__(256)
void convert_x_kernel(const float* __restrict__ X)
{
    if (blockIdx.x == 0 && threadIdx.x < 256) {
        g_flags[threadIdx.x] = 0; g_flags[threadIdx.x + 256] = 0;
    }
    size_t idx = (size_t)blockIdx.x * 256 + threadIdx.x;   // float4 index
    float4 v = ((const float4*)X)[idx];
    uint2 o;
    o.x = pack2h(__float2half(v.x), __float2half(v.y));
    o.y = pack2h(__float2half(v.z), __float2half(v.w));
    ((uint2*)g_Xh)[idx] = o;
}

__global__ __launch_bounds__(256)
void convert_w_kernel(const float* __restrict__ W)   // [k][n] fp32 -> [n][k] fp16
{
    __shared__ float st[32][33];
    const int n0 = blockIdx.x * 32;
    const int k0 = blockIdx.y * 32;
    const int tid = threadIdx.x;
    #pragma unroll
    for (int i = 0; i < 4; i++) {
        int id = tid + 256 * i;
        int kr = id >> 5, nc = id & 31;
        st[kr][nc] = W[(size_t)(k0 + kr) * GATES + n0 + nc];
    }
    __syncthreads();
    #pragma unroll
    for (int i = 0; i < 2; i++) {
        int id = tid + 256 * i;
        int nr = id >> 4, kc = id & 15;
        float v0 = st[2 * kc][nr], v1 = st[2 * kc + 1][nr];
        size_t o = (size_t)(n0 + nr) * (IN_DIM / 2) + (k0 >> 1) + kc;
        ((uint32_t*)g_Wth)[o] = pack2h(__float2half(v0), __float2half(v1));
    }
}

// =====================================================================
// Phase A: g_xw = x_f16 @ W_f16 + b   (unchanged from round 7)
// =====================================================================
#define STG_BYTES 30720
#define OFF_BHI   10240
#define PITCH     40

__global__ __launch_bounds__(256, 1)
void xw_gemm_kernel(const float* __restrict__ bias)
{
    extern __shared__ char sm[];
    const uint32_t smu = (uint32_t)__cvta_generic_to_shared(sm);

    const int tid  = threadIdx.x;
    const int lane = tid & 31;
    const int warp = tid >> 5;
    const int g    = lane >> 2;
    const int tg   = lane & 3;
    const int wm   = (warp & 3) * 32;
    const int wn   = (warp >> 2) * 128;
    const size_t m0 = (size_t)blockIdx.y * 128;
    const int    n0 = blockIdx.x * 256;

    const int rA = (lane & 7) | (((lane >> 3) & 1) << 3);
    const int cA = (lane >> 4) * 8;

    float acc[2][16][4];
    #pragma unroll
    for (int a = 0; a < 2; a++)
        #pragma unroll
        for (int b2 = 0; b2 < 16; b2++)
            #pragma unroll
            for (int c = 0; c < 4; c++) acc[a][b2][c] = 0.f;

    auto load_stage = [&](int s, int kk) {
        const int k0 = kk * 32;
        const uint32_t base = smu + s * STG_BYTES;
        #pragma unroll
        for (int i = 0; i < 2; i++) {
            int id  = tid + 256 * i;
            int row = id >> 2, ch = id & 3;
            const __half* src = g_Xh + (m0 + row) * (size_t)IN_DIM + k0 + ch * 8;
            cpasync16(base + (row * PITCH + ch * 8) * 2, src);
        }
        #pragma unroll
        for (int i = 0; i < 4; i++) {
            int id  = tid + 256 * i;
            int row = id >> 2, ch = id & 3;
            const __half* src = g_Wth + (size_t)(n0 + row) * IN_DIM + k0 + ch * 8;
            cpasync16(base + OFF_BHI + (row * PITCH + ch * 8) * 2, src);
        }
        CP_COMMIT();
    };

    load_stage(0, 0);
    load_stage(1, 1);

    for (int it = 0; it < 32; ++it) {
        CP_WAIT1();
        __syncthreads();
        if (it + 2 < 32) load_stage((it + 2) % 3, it + 2);
        else CP_COMMIT();

        const uint32_t sb = smu + (it % 3) * STG_BYTES;

        #pragma unroll
        for (int ks = 0; ks < 2; ks++) {
            uint32_t ah[2][4];
            #pragma unroll
            for (int mt = 0; mt < 2; mt++) {
                uint32_t ao = ((wm + mt * 16 + rA) * PITCH + ks * 16 + cA) * 2;
                ldsm_x4(ah[mt], sb + ao);
            }
            #pragma unroll
            for (int q = 0; q < 8; q++) {
                uint32_t bh[4];
                uint32_t bo = ((wn + q * 16 + rA) * PITCH + ks * 16 + cA) * 2;
                ldsm_x4(bh, sb + OFF_BHI + bo);
                uint32_t b0h[2] = {bh[0], bh[2]};
                uint32_t b1h[2] = {bh[1], bh[3]};
                #pragma unroll
                for (int mt = 0; mt < 2; mt++) {
                    mma16816h(acc[mt][2*q],   ah[mt], b0h);
                    mma16816h(acc[mt][2*q+1], ah[mt], b1h);
                }
            }
        }
    }

    #pragma unroll
    for (int mt = 0; mt < 2; mt++) {
        #pragma unroll
        for (int nt = 0; nt < 16; nt++) {
            size_t row = m0 + wm + mt * 16 + g;
            int    col = n0 + wn + nt * 8 + 2 * tg;
            float b0 = bias[col], b1 = bias[col + 1];
            float2 v0 = make_float2(acc[mt][nt][0] + b0, acc[mt][nt][1] + b1);
            float2 v1 = make_float2(acc[mt][nt][2] + b0, acc[mt][nt][3] + b1);
            *(float2*)(g_xw + row * GATES + col)       = v0;
            *(float2*)(g_xw + (row + 8) * GATES + col) = v1;
        }
    }
}

// =====================================================================
// Phase B v5: 128 threads, 4 independent warps. Warp = m-tile (16 batch
// rows), full K=1024, all 32 gate cols. In-register activations, direct
// fragment publish (no smem gbuf, no intra-step syncthreads, no shuffles).
// =====================================================================
#define WS_PITCH 520      // u32 per W column (520 % 32 == 8 -> conflict-free)

__global__ __launch_bounds__(128, 1)
void lstm_rec_kernel(const float* __restrict__ Wh, float* __restrict__ out,
                     int write_tail)
{
    extern __shared__ char smraw[];
    uint32_t* Wsf = (uint32_t*)smraw;                 // 32*520 u32 = 66560 B

    const int tid  = threadIdx.x;
    const int lane = tid & 31;
    const int warp = tid >> 5;       // m-tile: batch rows warp*16 .. +16
    const int g    = lane >> 2;
    const int tg   = lane & 3;
    const int wm   = warp * 16;
    const int j0   = blockIdx.x * 8;

    // one-time: W_h slice -> SMEM fragment layout (fp16)
    for (int i = tid; i < 32 * 1024; i += 128) {
        int c = i & 31;
        int k = i >> 5;
        int col = (c >> 3) * HID + j0 + (c & 7);
        float v = Wh[(size_t)k * GATES + col];
        int kt = k >> 4, t4 = (k >> 1) & 3, w = (k >> 3) & 1, hf = k & 1;
        int word = c * WS_PITCH + kt * 8 + t4 * 2 + w;
        ((__half*)Wsf)[word * 2 + hf] = __float2half(v);
    }
    __syncthreads();

    const int r0 = wm + g;            // global batch rows this lane owns
    const int r1 = wm + g + 8;
    const int jg = j0 + 2 * tg;       // hidden cols jg, jg+1

    // fragment-publish address components (constant over t)
    const int kt_p    = jg >> 4;
    const int fl_p    = g * 4 + tg;
    const int rg_base = ((j0 >> 3) & 1) << 1;
    const size_t pub0 = (size_t)kt_p * 512 + warp * 128 + fl_p * 4 + rg_base;

    float creg[4] = {0.f, 0.f, 0.f, 0.f};   // c for (r0,jg),(r0,jg+1),(r1,jg),(r1,jg+1)

    for (int t = 0; t < T_STEPS; t++) {
        // ---- prefetch xw gate slices (independent of the spin) ----
        const float* xwt = g_xw + (size_t)t * BATCH * GATES;
        float2 xg0[4], xg1[4];
        #pragma unroll
        for (int nt = 0; nt < 4; nt++) {
            xg0[nt] = *(const float2*)(xwt + (size_t)r0 * GATES + nt * HID + jg);
            xg1[nt] = *(const float2*)(xwt + (size_t)r1 * GATES + nt * HID + jg);
        }

        float acc[4][4];
        #pragma unroll
        for (int n2 = 0; n2 < 4; n2++)
            #pragma unroll
            for (int c2 = 0; c2 < 4; c2++) acc[n2][c2] = 0.f;

        if (t > 0) {
            if (lane == 0) {
                while (flag_acquire_ld(g_flags + (t - 1)) != FLAG_TARGET) { }
            }
            __syncwarp();

            const uint32_t* ab = g_hfrag + (size_t)(t - 1) * 32768
                                 + warp * 128 + lane * 4;
            uint4 H[4];
            #pragma unroll
            for (int q = 0; q < 4; q++) H[q] = *(const uint4*)(ab + q * 512);

            #pragma unroll 4
            for (int kt = 0; kt < 64; kt++) {
                int s = kt & 3;
                uint32_t ah[4] = {H[s].x, H[s].y, H[s].z, H[s].w};
                #pragma unroll
                for (int nt = 0; nt < 4; nt++) {
                    int c = nt * 8 + g;
                    uint2 bf = *(const uint2*)(Wsf + c * WS_PITCH + kt * 8 + tg * 2);
                    uint32_t bh[2] = {bf.x, bf.y};
                    mma16816h(acc[nt], ah, bh);
                }
                if (kt + 4 < 64) H[s] = *(const uint4*)(ab + (kt + 4) * 512);
            }
        }

        // ---- in-register activations: 4 (b,j) pairs per lane ----
        float hn[4], cn[4];
        #pragma unroll
        for (int c2 = 0; c2 < 4; c2++) {
            float xi, xf, xG, xo;
            if (c2 == 0)      { xi = xg0[0].x; xf = xg0[1].x; xG = xg0[2].x; xo = xg0[3].x; }
            else if (c2 == 1) { xi = xg0[0].y; xf = xg0[1].y; xG = xg0[2].y; xo = xg0[3].y; }
            else if (c2 == 2) { xi = xg1[0].x; xf = xg1[1].x; xG = xg1[2].x; xo = xg1[3].x; }
            else              { xi = xg1[0].y; xf = xg1[1].y; xG = xg1[2].y; xo = xg1[3].y; }
            float gi = acc[0][c2] + xi;
            float gf = acc[1][c2] + xf;
            float gg = acc[2][c2] + xG;
            float go = acc[3][c2] + xo;
            float iv = 1.f / (1.f + expf(-gi));
            float fv = 1.f / (1.f + expf(-gf));
            float gv = tanhf(gg);
            float ov = 1.f / (1.f + expf(-go));
            float c_ = fv * creg[c2] + iv * gv;
            float h_ = ov * tanhf(c_);
            creg[c2] = c_;
            cn[c2] = c_; hn[c2] = h_;
        }

        // ---- publish h fragments directly (no shuffle) ----
        {
            size_t fb = (size_t)t * 32768 + pub0;
            g_hfrag[fb]     = pack2h(__float2half(hn[0]), __float2half(hn[1]));  // r0
            g_hfrag[fb + 1] = pack2h(__float2half(hn[2]), __float2half(hn[3]));  // r1
        }
        __syncwarp();
        if (lane == 0) flag_release_add(g_flags + t);

        // ---- off-critical-path output stores ----
        float* hdst = out + (size_t)t * BATCH * HID;
        *(float2*)(hdst + (size_t)r0 * HID + jg) = make_float2(hn[0], hn[1]);
        *(float2*)(hdst + (size_t)r1 * HID + jg) = make_float2(hn[2], hn[3]);
        if (t == T_STEPS - 1 && write_tail) {
            size_t base = (size_t)T_STEPS * BATCH * HID;
            *(float2*)(out + base + (size_t)r0 * HID + jg) = make_float2(hn[0], hn[1]);
            *(float2*)(out + base + (size_t)r1 * HID + jg) = make_float2(hn[2], hn[3]);
            *(float2*)(out + base + BATCH * HID + (size_t)r0 * HID + jg) = make_float2(cn[0], cn[1]);
            *(float2*)(out + base + BATCH * HID + (size_t)r1 * HID + jg) = make_float2(cn[2], cn[3]);
        }
    }
}

// =====================================================================
extern "C" void kernel_launch(void* const* d_in, const int* in_sizes, int n_in,
                              void* d_out, int out_size)
{
    const float* x  = (const float*)d_in[0];
    const float* Wx = (const float*)d_in[1];
    const float* Wh = (const float*)d_in[2];
    const float* b  = (const float*)d_in[3];
    float* out = (float*)d_out;

    convert_x_kernel<<<(M_TOT * IN_DIM / 4) / 256, 256>>>(x);
    convert_w_kernel<<<dim3(GATES / 32, IN_DIM / 32), 256>>>(Wx);

    const int smemA = 3 * STG_BYTES;
    cudaFuncSetAttribute(xw_gemm_kernel,
                         cudaFuncAttributeMaxDynamicSharedMemorySize, smemA);
    dim3 gridA(GATES / 256, M_TOT / 128);
    xw_gemm_kernel<<<gridA, 256, smemA>>>(b);

    const int smemB = 32 * WS_PITCH * 4;   // 66560
    cudaFuncSetAttribute(lstm_rec_kernel,
                         cudaFuncAttributeMaxDynamicSharedMemorySize, smemB);
    int write_tail = (out_size > T_STEPS * BATCH * HID) ? 1 : 0;
    lstm_rec_kernel<<<NCTA, 128, smemB>>>(Wh, out, write_tail);
}